// round 14
// baseline (speedup 1.0000x reference)
#include <cuda_runtime.h>
#include <cstdint>

#define S_DIM 2048
#define NTHR 256
#define OUT_O_ELEMS 4194304ull
#define KV_ELEMS 4194304

__device__ float    g_inv[65536];          // 1/rowsum per (bh,row)
__device__ uint32_t g_kh[KV_ELEMS / 2];    // K fp16 (half2 words along d)
__device__ uint32_t g_vh[KV_ELEMS / 2];    // V fp16, k-paired

__device__ __forceinline__ uint32_t smem_u32(const void* p) {
  uint32_t a;
  asm("{ .reg .u64 t; cvta.to.shared.u64 t, %1; cvt.u32.u64 %0, t; }" : "=r"(a) : "l"(p));
  return a;
}
__device__ __forceinline__ uint32_t packh2(float lo, float hi) {
  uint32_t r; asm("cvt.rn.f16x2.f32 %0, %1, %2;" : "=r"(r) : "f"(hi), "f"(lo));
  return r;
}
__device__ __forceinline__ void mma16(float c[4], const uint32_t a[4],
                                      uint32_t b0, uint32_t b1) {
  asm volatile("mma.sync.aligned.m16n8k16.row.col.f32.f16.f16.f32 "
    "{%0,%1,%2,%3}, {%4,%5,%6,%7}, {%8,%9}, {%0,%1,%2,%3};"
    : "+f"(c[0]), "+f"(c[1]), "+f"(c[2]), "+f"(c[3])
    : "r"(a[0]), "r"(a[1]), "r"(a[2]), "r"(a[3]), "r"(b0), "r"(b1));
}
#define CP16(dst, src) asm volatile("cp.async.ca.shared.global [%0], [%1], 16;" :: "r"(dst), "l"(src) : "memory")
#define CP_COMMIT()    asm volatile("cp.async.commit_group;" ::: "memory")
#define CP_WAIT0()     asm volatile("cp.async.wait_group 0;" ::: "memory")

// =================== PREP : K,V -> fp16 (V k-paired) ===================
__global__ void __launch_bounds__(256)
kv_prep_kernel(const float* __restrict__ K, const float* __restrict__ V) {
  const int i = blockIdx.x * 256 + threadIdx.x;
  float4 k = ((const float4*)K)[i];
  ((uint2*)g_kh)[i] = make_uint2(packh2(k.x, k.y), packh2(k.z, k.w));
  const int k2g = i >> 5, d2 = i & 31;
  const float2* v0 = (const float2*)(V + (size_t)k2g * 128);
  float2 a = v0[d2], b = v0[32 + d2];
  ((uint2*)g_vh)[(size_t)k2g * 32 + d2] = make_uint2(packh2(a.x, b.x), packh2(a.y, b.y));
}

// ======================= PASS A : row sums (QT=64) =======================
#define QTA 64
#define A_QW 0
#define A_KW 2304
#define A_RW (A_KW + 9216)
#define A_SMB ((A_RW + 512) * 4)    // 48128 B

__global__ void __launch_bounds__(NTHR, 3)
rowsum_kernel(const float* __restrict__ Q) {
  extern __shared__ __align__(16) uint32_t smw[];
  const uint32_t sb = smem_u32(smw);
  const int tid = threadIdx.x;
  const int w = tid >> 5, lane = tid & 31;
  const int gid = lane >> 2, tg = lane & 3;
  const int bh = blockIdx.y;
  const int qt = (int)gridDim.x - 1 - (int)blockIdx.x;
  const int q0 = qt * QTA;

  const float* Qg = Q + ((size_t)bh * S_DIM + q0) * 64;
  const char* Kg = (const char*)g_kh + (size_t)bh * 262144;

  {
    #pragma unroll
    for (int it = 0; it < 4; ++it) {
      int idx = tid + it * NTHR;
      int r = idx >> 4, f = idx & 15;
      float4 v = ((const float4*)Qg)[idx];
      ((uint2*)(smw + A_QW + r * 36 + 2 * f))[0] =
          make_uint2(packh2(v.x * 0.125f, v.y * 0.125f), packh2(v.z * 0.125f, v.w * 0.125f));
    }
  }
  {
    #pragma unroll
    for (int it = 0; it < 4; ++it) {
      int idx = tid + it * NTHR;
      int r = idx >> 3, c = idx & 7;
      CP16(sb + A_KW * 4 + r * 144 + c * 16, Kg + r * 128 + c * 16);
    }
    CP_COMMIT();
  }
  __syncthreads();

  const int nkt = (q0 + QTA + 127) >> 7;
  float rs[8];
  #pragma unroll
  for (int u = 0; u < 8; ++u) rs[u] = 0.f;

  for (int tt = 0; tt < nkt; ++tt) {
    const int kc = tt << 7;
    CP_WAIT0();
    __syncthreads();
    if (tt + 1 < nkt) {
      const char* kg1 = Kg + (size_t)(kc + 128) * 128;
      uint32_t kd = sb + (A_KW + ((tt + 1) & 1) * 4608) * 4;
      #pragma unroll
      for (int it = 0; it < 4; ++it) {
        int idx = tid + it * NTHR;
        int r = idx >> 3, c = idx & 7;
        CP16(kd + r * 144 + c * 16, kg1 + r * 128 + c * 16);
      }
      CP_COMMIT();
    }
    const uint32_t* kb = smw + A_KW + (tt & 1) * 4608;
    const int nc0 = (16 * w + gid) * 36, nc1 = (16 * w + 8 + gid) * 36;
    const int cg0 = kc + 16 * w + 2 * tg, cg1 = cg0 + 8;

    uint32_t bf[4][4];
    #pragma unroll
    for (int s = 0; s < 4; ++s) {
      bf[s][0] = kb[nc0 + 8 * s + tg];
      bf[s][1] = kb[nc0 + 8 * s + 4 + tg];
      bf[s][2] = kb[nc1 + 8 * s + tg];
      bf[s][3] = kb[nc1 + 8 * s + 4 + tg];
    }

    #pragma unroll
    for (int a = 0; a < 4; ++a) {
      uint32_t af[4][4];
      #pragma unroll
      for (int s = 0; s < 4; ++s) {
        af[s][0] = smw[A_QW + (gid + 16 * a) * 36 + 8 * s + tg];
        af[s][1] = smw[A_QW + (gid + 8 + 16 * a) * 36 + 8 * s + tg];
        af[s][2] = smw[A_QW + (gid + 16 * a) * 36 + 8 * s + 4 + tg];
        af[s][3] = smw[A_QW + (gid + 8 + 16 * a) * 36 + 8 * s + 4 + tg];
      }
      float acc0[4] = {0.f, 0.f, 0.f, 0.f};
      float acc1[4] = {0.f, 0.f, 0.f, 0.f};
      #pragma unroll
      for (int s = 0; s < 4; ++s) {
        mma16(acc0, af[s], bf[s][0], bf[s][1]);
        mma16(acc1, af[s], bf[s][2], bf[s][3]);
      }
      const int ra = q0 + gid + 16 * a, rb = ra + 8;
      rs[2 * a] += ((cg0     <= ra) ? __expf(acc0[0]) : 0.f)
                 + ((cg0 + 1 <= ra) ? __expf(acc0[1]) : 0.f)
                 + ((cg1     <= ra) ? __expf(acc1[0]) : 0.f)
                 + ((cg1 + 1 <= ra) ? __expf(acc1[1]) : 0.f);
      rs[2 * a + 1] += ((cg0     <= rb) ? __expf(acc0[2]) : 0.f)
                     + ((cg0 + 1 <= rb) ? __expf(acc0[3]) : 0.f)
                     + ((cg1     <= rb) ? __expf(acc1[2]) : 0.f)
                     + ((cg1 + 1 <= rb) ? __expf(acc1[3]) : 0.f);
    }
  }

  #pragma unroll
  for (int u = 0; u < 8; ++u) {
    rs[u] += __shfl_xor_sync(~0u, rs[u], 1);
    rs[u] += __shfl_xor_sync(~0u, rs[u], 2);
  }
  float* red = (float*)(smw + A_RW);
  if (tg == 0) {
    #pragma unroll
    for (int a = 0; a < 4; ++a) {
      red[w * 64 + gid + 16 * a]     = rs[2 * a];
      red[w * 64 + gid + 8 + 16 * a] = rs[2 * a + 1];
    }
  }
  __syncthreads();
  if (tid < 64) {
    float s = 0.f;
    #pragma unroll
    for (int i = 0; i < 8; ++i) s += red[i * 64 + tid];
    g_inv[bh * S_DIM + q0 + tid] = 1.0f / s;
  }
}

// ========== PASS B : W + O (QT=32, KT=64, 3 CTAs/SM) ==========
#define QTB 32
#define B_QW 0                         // 32*36 = 1152
#define B_KW 1152                      // 2 * 64*36 = 4608
#define B_VW (B_KW + 4608)             // 5760 : V 2 * 32*68 = 4352
#define B_PW (B_VW + 4352)             // 10112 : P 32*36 = 1152
#define B_SMB ((B_PW + 1152) * 4)      // 45056 B -> 3 CTAs/SM

__global__ void __launch_bounds__(NTHR, 3)
attn_pb_kernel(const float* __restrict__ Q, float* __restrict__ out) {
  extern __shared__ __align__(16) uint32_t smw[];
  const uint32_t sb = smem_u32(smw);
  const int tid = threadIdx.x;
  const int w = tid >> 5, lane = tid & 31;
  const int gid = lane >> 2, tg = lane & 3;
  const int bh = blockIdx.y;
  const int qt = (int)gridDim.x - 1 - (int)blockIdx.x;
  const int q0 = qt * QTB;

  const float* Qg = Q + ((size_t)bh * S_DIM + q0) * 64;
  const char* Kg = (const char*)g_kh + (size_t)bh * 262144;
  const char* Vg = (const char*)g_vh + (size_t)bh * 262144;
  float* Og = out + ((size_t)bh * S_DIM + q0) * 64;
  float* Wg = out + OUT_O_ELEMS + ((size_t)bh * S_DIM + q0) * (size_t)S_DIM;

  const float iv0 = g_inv[bh * S_DIM + q0 + gid];
  const float iv1 = g_inv[bh * S_DIM + q0 + gid + 8];
  const float iv2 = g_inv[bh * S_DIM + q0 + gid + 16];
  const float iv3 = g_inv[bh * S_DIM + q0 + gid + 24];

  { // stage Q (x 1/8) as fp16
    #pragma unroll
    for (int it = 0; it < 2; ++it) {
      int idx = tid + it * NTHR;
      int r = idx >> 4, f = idx & 15;
      float4 v = ((const float4*)Qg)[idx];
      ((uint2*)(smw + B_QW + r * 36 + 2 * f))[0] =
          make_uint2(packh2(v.x * 0.125f, v.y * 0.125f), packh2(v.z * 0.125f, v.w * 0.125f));
    }
  }
  { // prolog: K(0) + V(0)
    #pragma unroll
    for (int it = 0; it < 2; ++it) {
      int idx = tid + it * NTHR;
      int r = idx >> 3, c = idx & 7;
      CP16(sb + B_KW * 4 + r * 144 + c * 16, Kg + r * 128 + c * 16);
    }
    #pragma unroll
    for (int it = 0; it < 2; ++it) {
      int idx = tid + it * NTHR;
      int k2 = idx >> 4, c = idx & 15;
      CP16(sb + B_VW * 4 + k2 * 272 + (((c << 2) + 4 * (k2 & 15)) & 63) * 4,
           Vg + k2 * 256 + c * 16);
    }
    CP_COMMIT();
  }
  __syncthreads();

  const int nkt = (q0 + QTB + 63) >> 6;
  float oc[4][4];
  #pragma unroll
  for (int j = 0; j < 4; ++j)
    #pragma unroll
    for (int u = 0; u < 4; ++u) oc[j][u] = 0.f;

  // PV role: warp = (atom a2 = w>>2, d-half dh = (w>>1)&1, k-slice s2 = w&1)
  const int a2 = w >> 2, dh = (w >> 1) & 1, s2 = w & 1;
  const int rpa = (gid + 16 * a2) * 36, rpb = rpa + 8 * 36;
  uint32_t* pw = smw + B_PW;

  for (int tt = 0; tt < nkt; ++tt) {
    const int kc = tt << 6;
    CP_WAIT0();
    __syncthreads();
    if (tt + 1 < nkt) {   // prefetch K(tt+1), V(tt+1)
      const char* kg1 = Kg + (size_t)(kc + 64) * 128;
      const char* vg1 = Vg + (size_t)(kc >> 1) * 256 + 32 * 256;
      uint32_t kd = sb + (B_KW + ((tt + 1) & 1) * 2304) * 4;
      uint32_t vd = sb + (B_VW + ((tt + 1) & 1) * 2176) * 4;
      #pragma unroll
      for (int it = 0; it < 2; ++it) {
        int idx = tid + it * NTHR;
        int r = idx >> 3, c = idx & 7;
        CP16(kd + r * 144 + c * 16, kg1 + r * 128 + c * 16);
      }
      #pragma unroll
      for (int it = 0; it < 2; ++it) {
        int idx = tid + it * NTHR;
        int k2 = idx >> 4, c = idx & 15;
        CP16(vd + k2 * 272 + (((c << 2) + 4 * (k2 & 15)) & 63) * 4,
             vg1 + k2 * 256 + c * 16);
      }
      CP_COMMIT();
    }
    const uint32_t* kb = smw + B_KW + (tt & 1) * 2304;
    const uint32_t* vb = smw + B_VW + (tt & 1) * 2176;

    // ---- QK: warp's n8 strip, both atoms; W + P(smem) from regs ----
    const int ncol = (8 * w + gid) * 36;
    const int cg0 = kc + 8 * w + 2 * tg;
    const int k2w = 4 * w + tg;
    uint32_t bf[4][2];
    #pragma unroll
    for (int s = 0; s < 4; ++s) {
      bf[s][0] = kb[ncol + 8 * s + tg];
      bf[s][1] = kb[ncol + 8 * s + 4 + tg];
    }
    #pragma unroll
    for (int a = 0; a < 2; ++a) {
      uint32_t af[4][4];
      #pragma unroll
      for (int s = 0; s < 4; ++s) {
        af[s][0] = smw[B_QW + (gid + 16 * a) * 36 + 8 * s + tg];
        af[s][1] = smw[B_QW + (gid + 8 + 16 * a) * 36 + 8 * s + tg];
        af[s][2] = smw[B_QW + (gid + 16 * a) * 36 + 8 * s + 4 + tg];
        af[s][3] = smw[B_QW + (gid + 8 + 16 * a) * 36 + 8 * s + 4 + tg];
      }
      float acc[4] = {0.f, 0.f, 0.f, 0.f};
      #pragma unroll
      for (int s = 0; s < 4; ++s)
        mma16(acc, af[s], bf[s][0], bf[s][1]);
      const int ra = q0 + gid + 16 * a, rb = ra + 8;
      const float iva = a ? iv2 : iv0, ivb = a ? iv3 : iv1;
      float e00 = (cg0     <= ra) ? __expf(acc[0]) * iva : 0.f;
      float e01 = (cg0 + 1 <= ra) ? __expf(acc[1]) * iva : 0.f;
      float e10 = (cg0     <= rb) ? __expf(acc[2]) * ivb : 0.f;
      float e11 = (cg0 + 1 <= rb) ? __expf(acc[3]) * ivb : 0.f;
      const int rla = gid + 16 * a, rlb = rla + 8;
      *(float2*)&Wg[(size_t)rla * S_DIM + cg0] = make_float2(e00, e01);
      *(float2*)&Wg[(size_t)rlb * S_DIM + cg0] = make_float2(e10, e11);
      pw[rla * 36 + k2w] = packh2(e00, e01);
      pw[rlb * 36 + k2w] = packh2(e10, e11);
    }
    __syncthreads();   // P tile complete before cross-warp PV reads

    // ---- PV: warp (a2, dh, s2): 16 rows x 32 d-cols over k-slice ----
    #pragma unroll
    for (int c = 0; c < 2; ++c) {
      const int base = 16 * s2 + 8 * c;
      uint32_t pa[4];
      pa[0] = pw[rpa + base + tg];
      pa[1] = pw[rpb + base + tg];
      pa[2] = pw[rpa + base + 4 + tg];
      pa[3] = pw[rpb + base + 4 + tg];
      const int k2a = base + tg, k2b = base + 4 + tg;
      const int swa = 4 * (k2a & 15), swb = 4 * (k2b & 15);
      #pragma unroll
      for (int j = 0; j < 4; ++j) {
        const int d = 32 * dh + 8 * j + gid;
        uint32_t b0 = vb[k2a * 68 + ((d + swa) & 63)];
        uint32_t b1 = vb[k2b * 68 + ((d + swb) & 63)];
        mma16(oc[j], pa, b0, b1);
      }
    }
  }

  // ---- W zero tail ----
  {
    const int ktend = nkt << 6;
    const int r = tid >> 3, f = tid & 7;
    float4* wrow = (float4*)(Wg + (size_t)r * S_DIM);
    const float4 z = make_float4(0.f, 0.f, 0.f, 0.f);
    for (int c4 = (ktend >> 2) + f; c4 < (S_DIM >> 2); c4 += 8) wrow[c4] = z;
  }

  // ---- O merge: 2 k-slice partials per (atom, d-half) via smem reuse ----
  __syncthreads();
  float* smf = (float*)smw;
  {
    float* osc = &smf[w * 544];   // 16 rows x 32 cols (+2 pad) per warp
    #pragma unroll
    for (int j = 0; j < 4; ++j) {
      *(float2*)&osc[gid * 34 + 8 * j + 2 * tg]       = make_float2(oc[j][0], oc[j][1]);
      *(float2*)&osc[(gid + 8) * 34 + 8 * j + 2 * tg] = make_float2(oc[j][2], oc[j][3]);
    }
  }
  __syncthreads();
  #pragma unroll
  for (int it = 0; it < 8; ++it) {
    const int e = tid + it * NTHR;
    const int r = e >> 6, d = e & 63;          // r 0..31, d 0..63
    const int wbase = (r >> 4) * 4 + (d >> 5) * 2;
    const int rl = r & 15, dl = d & 31;
    float s = smf[wbase * 544 + rl * 34 + dl]
            + smf[(wbase + 1) * 544 + rl * 34 + dl];
    Og[r * 64 + d] = s;
  }
}

extern "C" void kernel_launch(void* const* d_in, const int* in_sizes, int n_in,
                              void* d_out, int out_size) {
  (void)in_sizes; (void)n_in; (void)out_size;
  const float* q = (const float*)d_in[0];
  const float* k = (const float*)d_in[1];
  const float* v = (const float*)d_in[2];
  float* out = (float*)d_out;

  cudaFuncSetAttribute(rowsum_kernel,
                       cudaFuncAttributeMaxDynamicSharedMemorySize, A_SMB);
  cudaFuncSetAttribute(attn_pb_kernel,
                       cudaFuncAttributeMaxDynamicSharedMemorySize, B_SMB);
  kv_prep_kernel<<<KV_ELEMS / 4 / 256, 256>>>(k, v);
  rowsum_kernel<<<dim3(S_DIM / QTA, 32), NTHR, A_SMB>>>(q);
  attn_pb_kernel<<<dim3(S_DIM / QTB, 32), NTHR, B_SMB>>>(q, out);
}

// round 15
// speedup vs baseline: 1.0086x; 1.0086x over previous
#include <cuda_runtime.h>
#include <cstdint>

#define S_DIM 2048
#define NTHR 256
#define OUT_O_ELEMS 4194304ull
#define KV_ELEMS 4194304

__device__ float    g_inv[65536];          // 1/rowsum per (bh,row)
__device__ uint32_t g_kh[KV_ELEMS / 2];    // K fp16 (half2 words along d)
__device__ uint32_t g_vh[KV_ELEMS / 2];    // V fp16, k-paired

__device__ __forceinline__ uint32_t smem_u32(const void* p) {
  uint32_t a;
  asm("{ .reg .u64 t; cvta.to.shared.u64 t, %1; cvt.u32.u64 %0, t; }" : "=r"(a) : "l"(p));
  return a;
}
__device__ __forceinline__ uint32_t packh2(float lo, float hi) {
  uint32_t r; asm("cvt.rn.f16x2.f32 %0, %1, %2;" : "=r"(r) : "f"(hi), "f"(lo));
  return r;
}
__device__ __forceinline__ void mma16(float c[4], const uint32_t a[4],
                                      uint32_t b0, uint32_t b1) {
  asm volatile("mma.sync.aligned.m16n8k16.row.col.f32.f16.f16.f32 "
    "{%0,%1,%2,%3}, {%4,%5,%6,%7}, {%8,%9}, {%0,%1,%2,%3};"
    : "+f"(c[0]), "+f"(c[1]), "+f"(c[2]), "+f"(c[3])
    : "r"(a[0]), "r"(a[1]), "r"(a[2]), "r"(a[3]), "r"(b0), "r"(b1));
}
#define CP16(dst, src) asm volatile("cp.async.ca.shared.global [%0], [%1], 16;" :: "r"(dst), "l"(src) : "memory")
#define CP_COMMIT()    asm volatile("cp.async.commit_group;" ::: "memory")
#define CP_WAIT0()     asm volatile("cp.async.wait_group 0;" ::: "memory")

// =================== PREP : K,V -> fp16 (V k-paired) ===================
__global__ void __launch_bounds__(256)
kv_prep_kernel(const float* __restrict__ K, const float* __restrict__ V) {
  const int i = blockIdx.x * 256 + threadIdx.x;
  float4 k = ((const float4*)K)[i];
  ((uint2*)g_kh)[i] = make_uint2(packh2(k.x, k.y), packh2(k.z, k.w));
  const int k2g = i >> 5, d2 = i & 31;
  const float2* v0 = (const float2*)(V + (size_t)k2g * 128);
  float2 a = v0[d2], b = v0[32 + d2];
  ((uint2*)g_vh)[(size_t)k2g * 32 + d2] = make_uint2(packh2(a.x, b.x), packh2(a.y, b.y));
}

// ======== PASS A' : rowsums + unnormalized O (QT=32, in-reg PV) ========
#define QTC 32
#define C_QW 0                      // 32*36 = 1152
#define C_KW 1152                   // 2 * 128*36 = 9216
#define C_VW (C_KW + 9216)          // 10368 : V 2 * 64*68 = 8704
#define C_RW (C_VW + 8704)          // 19072 : red 256
#define C_IW (C_RW + 256)           // 19328 : inv 32
#define C_SMB ((C_IW + 32) * 4)     // 77440 B -> 2 CTAs/SM

__global__ void __launch_bounds__(NTHR, 2)
rowsum_o_kernel(const float* __restrict__ Q, float* __restrict__ out) {
  extern __shared__ __align__(16) uint32_t smw[];
  const uint32_t sb = smem_u32(smw);
  const int tid = threadIdx.x;
  const int w = tid >> 5, lane = tid & 31;
  const int gid = lane >> 2, tg = lane & 3;
  const int bh = blockIdx.y;
  const int qt = (int)gridDim.x - 1 - (int)blockIdx.x;
  const int q0 = qt * QTC;

  const float* Qg = Q + ((size_t)bh * S_DIM + q0) * 64;
  const char* Kg = (const char*)g_kh + (size_t)bh * 262144;
  const char* Vg = (const char*)g_vh + (size_t)bh * 262144;
  float* Og = out + ((size_t)bh * S_DIM + q0) * 64;

  { // stage Q (x 1/8) as fp16
    #pragma unroll
    for (int it = 0; it < 2; ++it) {
      int idx = tid + it * NTHR;
      int r = idx >> 4, f = idx & 15;
      float4 v = ((const float4*)Qg)[idx];
      ((uint2*)(smw + C_QW + r * 36 + 2 * f))[0] =
          make_uint2(packh2(v.x * 0.125f, v.y * 0.125f), packh2(v.z * 0.125f, v.w * 0.125f));
    }
  }
  { // prolog: K(0) + V(0)
    #pragma unroll
    for (int it = 0; it < 4; ++it) {
      int idx = tid + it * NTHR;
      int r = idx >> 3, c = idx & 7;
      CP16(sb + C_KW * 4 + r * 144 + c * 16, Kg + r * 128 + c * 16);
    }
    #pragma unroll
    for (int it = 0; it < 4; ++it) {
      int idx = tid + it * NTHR;
      int k2 = idx >> 4, c = idx & 15;
      CP16(sb + C_VW * 4 + k2 * 272 + (((c << 2) + 4 * (k2 & 15)) & 63) * 4,
           Vg + k2 * 256 + c * 16);
    }
    CP_COMMIT();
  }
  __syncthreads();

  const int nkt = (q0 + QTC + 127) >> 7;
  float rs[4] = {0.f, 0.f, 0.f, 0.f};
  float oc[2][8][4];
  #pragma unroll
  for (int a = 0; a < 2; ++a)
    #pragma unroll
    for (int j = 0; j < 8; ++j)
      #pragma unroll
      for (int u = 0; u < 4; ++u) oc[a][j][u] = 0.f;

  const int k2a = 8 * w + tg, k2b = 8 * w + 4 + tg;       // warp's V rows
  const int swa = 4 * (k2a & 15), swb = 4 * (k2b & 15);

  for (int tt = 0; tt < nkt; ++tt) {
    const int kc = tt << 7;
    CP_WAIT0();
    __syncthreads();
    if (tt + 1 < nkt) {   // prefetch K(tt+1), V(tt+1)
      const char* kg1 = Kg + (size_t)(kc + 128) * 128;
      const char* vg1 = Vg + (size_t)(kc >> 1) * 256 + 64 * 256;
      uint32_t kd = sb + (C_KW + ((tt + 1) & 1) * 4608) * 4;
      uint32_t vd = sb + (C_VW + ((tt + 1) & 1) * 4352) * 4;
      #pragma unroll
      for (int it = 0; it < 4; ++it) {
        int idx = tid + it * NTHR;
        int r = idx >> 3, c = idx & 7;
        CP16(kd + r * 144 + c * 16, kg1 + r * 128 + c * 16);
      }
      #pragma unroll
      for (int it = 0; it < 4; ++it) {
        int idx = tid + it * NTHR;
        int k2 = idx >> 4, c = idx & 15;
        CP16(vd + k2 * 272 + (((c << 2) + 4 * (k2 & 15)) & 63) * 4,
             vg1 + k2 * 256 + c * 16);
      }
      CP_COMMIT();
    }
    const uint32_t* kb = smw + C_KW + (tt & 1) * 4608;
    const uint32_t* vb = smw + C_VW + (tt & 1) * 4352;

    const int nc0 = (16 * w + gid) * 36, nc1 = (16 * w + 8 + gid) * 36;
    const int cg0 = kc + 16 * w + 2 * tg, cg1 = cg0 + 8;

    #pragma unroll
    for (int a = 0; a < 2; ++a) {
      uint32_t af[4][4];
      #pragma unroll
      for (int s = 0; s < 4; ++s) {
        af[s][0] = smw[C_QW + (gid + 16 * a) * 36 + 8 * s + tg];
        af[s][1] = smw[C_QW + (gid + 8 + 16 * a) * 36 + 8 * s + tg];
        af[s][2] = smw[C_QW + (gid + 16 * a) * 36 + 8 * s + 4 + tg];
        af[s][3] = smw[C_QW + (gid + 8 + 16 * a) * 36 + 8 * s + 4 + tg];
      }
      float acc0[4] = {0.f, 0.f, 0.f, 0.f};
      float acc1[4] = {0.f, 0.f, 0.f, 0.f};
      #pragma unroll
      for (int s = 0; s < 4; ++s) {
        mma16(acc0, af[s], kb[nc0 + 8 * s + tg], kb[nc0 + 8 * s + 4 + tg]);
        mma16(acc1, af[s], kb[nc1 + 8 * s + tg], kb[nc1 + 8 * s + 4 + tg]);
      }
      const int ra = q0 + gid + 16 * a, rb = ra + 8;
      float e000 = (cg0     <= ra) ? __expf(acc0[0]) : 0.f;
      float e001 = (cg0 + 1 <= ra) ? __expf(acc0[1]) : 0.f;
      float e010 = (cg0     <= rb) ? __expf(acc0[2]) : 0.f;
      float e011 = (cg0 + 1 <= rb) ? __expf(acc0[3]) : 0.f;
      float e100 = (cg1     <= ra) ? __expf(acc1[0]) : 0.f;
      float e101 = (cg1 + 1 <= ra) ? __expf(acc1[1]) : 0.f;
      float e110 = (cg1     <= rb) ? __expf(acc1[2]) : 0.f;
      float e111 = (cg1 + 1 <= rb) ? __expf(acc1[3]) : 0.f;
      rs[2 * a]     += e000 + e001 + e100 + e101;
      rs[2 * a + 1] += e010 + e011 + e110 + e111;

      uint32_t pa[4];
      pa[0] = packh2(e000, e001);
      pa[1] = packh2(e010, e011);
      pa[2] = packh2(e100, e101);
      pa[3] = packh2(e110, e111);
      #pragma unroll
      for (int j = 0; j < 8; ++j) {
        const int d = 8 * j + gid;
        uint32_t b0 = vb[k2a * 68 + ((d + swa) & 63)];
        uint32_t b1 = vb[k2b * 68 + ((d + swb) & 63)];
        mma16(oc[a][j], pa, b0, b1);
      }
    }
  }

  // ---- rowsum reduce -> inv (smem + g_inv) ----
  #pragma unroll
  for (int u = 0; u < 4; ++u) {
    rs[u] += __shfl_xor_sync(~0u, rs[u], 1);
    rs[u] += __shfl_xor_sync(~0u, rs[u], 2);
  }
  float* red = (float*)(smw + C_RW);
  if (tg == 0) {
    red[w * 32 + gid]      = rs[0];
    red[w * 32 + gid + 8]  = rs[1];
    red[w * 32 + gid + 16] = rs[2];
    red[w * 32 + gid + 24] = rs[3];
  }
  __syncthreads();
  if (tid < 32) {
    float s = 0.f;
    #pragma unroll
    for (int i = 0; i < 8; ++i) s += red[i * 32 + tid];
    const float iv = 1.0f / s;
    ((float*)(smw + C_IW))[tid] = iv;
    g_inv[bh * S_DIM + q0 + tid] = iv;
  }
  __syncthreads();

  // ---- O merge: 8 per-warp k-slice partials via smem reuse ----
  float* smf = (float*)smw;
  {
    float* osc = &smf[w * (32 * 66)];   // 32 rows x 64 d (+2 pad)
    #pragma unroll
    for (int a = 0; a < 2; ++a)
      #pragma unroll
      for (int j = 0; j < 8; ++j) {
        *(float2*)&osc[(gid + 16 * a) * 66 + j * 8 + 2 * tg] =
            make_float2(oc[a][j][0], oc[a][j][1]);
        *(float2*)&osc[(gid + 8 + 16 * a) * 66 + j * 8 + 2 * tg] =
            make_float2(oc[a][j][2], oc[a][j][3]);
      }
  }
  __syncthreads();
  const float* invs = (const float*)(smw + C_IW);
  #pragma unroll
  for (int it = 0; it < 8; ++it) {
    const int e = tid + it * NTHR;
    const int r = e >> 6, d = e & 63;
    float s = 0.f;
    #pragma unroll
    for (int p = 0; p < 8; ++p) s += smf[p * (32 * 66) + r * 66 + d];
    Og[r * 64 + d] = s * invs[r];
  }
}

// ============ PASS B' : pure W streamer (QT=32, occ 4) ============
#define QTB 32
#define B_QW 0                      // 1152
#define B_KW 1152                   // 2 * 4608
#define B_SMB ((B_KW + 9216) * 4)   // 41472 B -> smem allows 5 CTAs; regs -> 4

__global__ void __launch_bounds__(NTHR, 4)
attn_w_kernel(const float* __restrict__ Q, float* __restrict__ out) {
  extern __shared__ __align__(16) uint32_t smw[];
  const uint32_t sb = smem_u32(smw);
  const int tid = threadIdx.x;
  const int w = tid >> 5, lane = tid & 31;
  const int gid = lane >> 2, tg = lane & 3;
  const int bh = blockIdx.y;
  const int qt = (int)gridDim.x - 1 - (int)blockIdx.x;
  const int q0 = qt * QTB;

  const float* Qg = Q + ((size_t)bh * S_DIM + q0) * 64;
  const char* Kg = (const char*)g_kh + (size_t)bh * 262144;
  float* Wg = out + OUT_O_ELEMS + ((size_t)bh * S_DIM + q0) * (size_t)S_DIM;

  const float iv0 = g_inv[bh * S_DIM + q0 + gid];
  const float iv1 = g_inv[bh * S_DIM + q0 + gid + 8];
  const float iv2 = g_inv[bh * S_DIM + q0 + gid + 16];
  const float iv3 = g_inv[bh * S_DIM + q0 + gid + 24];

  { // stage Q (x 1/8) as fp16
    #pragma unroll
    for (int it = 0; it < 2; ++it) {
      int idx = tid + it * NTHR;
      int r = idx >> 4, f = idx & 15;
      float4 v = ((const float4*)Qg)[idx];
      ((uint2*)(smw + B_QW + r * 36 + 2 * f))[0] =
          make_uint2(packh2(v.x * 0.125f, v.y * 0.125f), packh2(v.z * 0.125f, v.w * 0.125f));
    }
  }
  { // prolog: K(0)
    #pragma unroll
    for (int it = 0; it < 4; ++it) {
      int idx = tid + it * NTHR;
      int r = idx >> 3, c = idx & 7;
      CP16(sb + B_KW * 4 + r * 144 + c * 16, Kg + r * 128 + c * 16);
    }
    CP_COMMIT();
  }
  __syncthreads();

  const int nkt = (q0 + QTB + 127) >> 7;

  for (int tt = 0; tt < nkt; ++tt) {
    const int kc = tt << 7;
    CP_WAIT0();
    __syncthreads();
    if (tt + 1 < nkt) {
      const char* kg1 = Kg + (size_t)(kc + 128) * 128;
      uint32_t kd = sb + (B_KW + ((tt + 1) & 1) * 4608) * 4;
      #pragma unroll
      for (int it = 0; it < 4; ++it) {
        int idx = tid + it * NTHR;
        int r = idx >> 3, c = idx & 7;
        CP16(kd + r * 144 + c * 16, kg1 + r * 128 + c * 16);
      }
      CP_COMMIT();
    }
    const uint32_t* kb = smw + B_KW + (tt & 1) * 4608;
    const int nc0 = (16 * w + gid) * 36, nc1 = (16 * w + 8 + gid) * 36;
    const int cg0 = kc + 16 * w + 2 * tg, cg1 = cg0 + 8;

    #pragma unroll
    for (int a = 0; a < 2; ++a) {
      uint32_t af[4][4];
      #pragma unroll
      for (int s = 0; s < 4; ++s) {
        af[s][0] = smw[B_QW + (gid + 16 * a) * 36 + 8 * s + tg];
        af[s][1] = smw[B_QW + (gid + 8 + 16 * a) * 36 + 8 * s + tg];
        af[s][2] = smw[B_QW + (gid + 16 * a) * 36 + 8 * s + 4 + tg];
        af[s][3] = smw[B_QW + (gid + 8 + 16 * a) * 36 + 8 * s + 4 + tg];
      }
      float acc0[4] = {0.f, 0.f, 0.f, 0.f};
      float acc1[4] = {0.f, 0.f, 0.f, 0.f};
      #pragma unroll
      for (int s = 0; s < 4; ++s) {
        mma16(acc0, af[s], kb[nc0 + 8 * s + tg], kb[nc0 + 8 * s + 4 + tg]);
        mma16(acc1, af[s], kb[nc1 + 8 * s + tg], kb[nc1 + 8 * s + 4 + tg]);
      }
      const int ra = q0 + gid + 16 * a, rb = ra + 8;
      const float iva = a ? iv2 : iv0, ivb = a ? iv3 : iv1;
      const int rla = gid + 16 * a, rlb = rla + 8;
      *(float2*)&Wg[(size_t)rla * S_DIM + cg0] = make_float2(
          (cg0     <= ra) ? __expf(acc0[0]) * iva : 0.f,
          (cg0 + 1 <= ra) ? __expf(acc0[1]) * iva : 0.f);
      *(float2*)&Wg[(size_t)rlb * S_DIM + cg0] = make_float2(
          (cg0     <= rb) ? __expf(acc0[2]) * ivb : 0.f,
          (cg0 + 1 <= rb) ? __expf(acc0[3]) * ivb : 0.f);
      *(float2*)&Wg[(size_t)rla * S_DIM + cg1] = make_float2(
          (cg1     <= ra) ? __expf(acc1[0]) * iva : 0.f,
          (cg1 + 1 <= ra) ? __expf(acc1[1]) * iva : 0.f);
      *(float2*)&Wg[(size_t)rlb * S_DIM + cg1] = make_float2(
          (cg1     <= rb) ? __expf(acc1[2]) * ivb : 0.f,
          (cg1 + 1 <= rb) ? __expf(acc1[3]) * ivb : 0.f);
    }
  }

  // ---- W zero tail ----
  {
    const int ktend = nkt << 7;
    const int r = tid >> 3, f = tid & 7;
    float4* wrow = (float4*)(Wg + (size_t)r * S_DIM);
    const float4 z = make_float4(0.f, 0.f, 0.f, 0.f);
    for (int c4 = (ktend >> 2) + f; c4 < (S_DIM >> 2); c4 += 8) wrow[c4] = z;
  }
}

extern "C" void kernel_launch(void* const* d_in, const int* in_sizes, int n_in,
                              void* d_out, int out_size) {
  (void)in_sizes; (void)n_in; (void)out_size;
  const float* q = (const float*)d_in[0];
  const float* k = (const float*)d_in[1];
  const float* v = (const float*)d_in[2];
  float* out = (float*)d_out;

  cudaFuncSetAttribute(rowsum_o_kernel,
                       cudaFuncAttributeMaxDynamicSharedMemorySize, C_SMB);
  cudaFuncSetAttribute(attn_w_kernel,
                       cudaFuncAttributeMaxDynamicSharedMemorySize, B_SMB);
  kv_prep_kernel<<<KV_ELEMS / 4 / 256, 256>>>(k, v);
  rowsum_o_kernel<<<dim3(S_DIM / QTC, 32), NTHR, C_SMB>>>(q, out);
  attn_w_kernel<<<dim3(S_DIM / QTB, 32), NTHR, B_SMB>>>(q, out);
}

// round 16
// speedup vs baseline: 1.0998x; 1.0905x over previous
#include <cuda_runtime.h>
#include <cstdint>

#define S_DIM 2048
#define QT 32
#define KT 128
#define NTHR 256
#define OUT_O_ELEMS 4194304ull
#define KV_ELEMS 4194304

__device__ float    g_inv[65536];          // 1/rowsum per (bh,row)
__device__ uint32_t g_kh[KV_ELEMS / 2];    // K fp16 (half2 words along d)
__device__ uint32_t g_vh[KV_ELEMS / 2];    // V fp16, k-paired

__device__ __forceinline__ uint32_t smem_u32(const void* p) {
  uint32_t a;
  asm("{ .reg .u64 t; cvta.to.shared.u64 t, %1; cvt.u32.u64 %0, t; }" : "=r"(a) : "l"(p));
  return a;
}
__device__ __forceinline__ uint32_t packh2(float lo, float hi) {
  uint32_t r; asm("cvt.rn.f16x2.f32 %0, %1, %2;" : "=r"(r) : "f"(hi), "f"(lo));
  return r;
}
__device__ __forceinline__ void mma16(float c[4], const uint32_t a[4],
                                      uint32_t b0, uint32_t b1) {
  asm volatile("mma.sync.aligned.m16n8k16.row.col.f32.f16.f16.f32 "
    "{%0,%1,%2,%3}, {%4,%5,%6,%7}, {%8,%9}, {%0,%1,%2,%3};"
    : "+f"(c[0]), "+f"(c[1]), "+f"(c[2]), "+f"(c[3])
    : "r"(a[0]), "r"(a[1]), "r"(a[2]), "r"(a[3]), "r"(b0), "r"(b1));
}
__device__ __forceinline__ void stg_cs2(float* p, float x, float y) {
  asm volatile("st.global.cs.v2.f32 [%0], {%1, %2};" :: "l"(p), "f"(x), "f"(y) : "memory");
}
__device__ __forceinline__ void stg_cs4z(float* p) {
  asm volatile("st.global.cs.v4.f32 [%0], {%1, %1, %1, %1};" :: "l"(p), "f"(0.f) : "memory");
}
#define CP16(dst, src) asm volatile("cp.async.ca.shared.global [%0], [%1], 16;" :: "r"(dst), "l"(src) : "memory")
#define CP_COMMIT()    asm volatile("cp.async.commit_group;" ::: "memory")
#define CP_WAIT0()     asm volatile("cp.async.wait_group 0;" ::: "memory")

// =================== PREP : K,V -> fp16 (V k-paired) ===================
__global__ void __launch_bounds__(256)
kv_prep_kernel(const float* __restrict__ K, const float* __restrict__ V) {
  const int i = blockIdx.x * 256 + threadIdx.x;
  float4 k = ((const float4*)K)[i];
  ((uint2*)g_kh)[i] = make_uint2(packh2(k.x, k.y), packh2(k.z, k.w));
  const int k2g = i >> 5, d2 = i & 31;
  const float2* v0 = (const float2*)(V + (size_t)k2g * 128);
  float2 a = v0[d2], b = v0[32 + d2];
  ((uint2*)g_vh)[(size_t)k2g * 32 + d2] = make_uint2(packh2(a.x, b.x), packh2(a.y, b.y));
}

// ======================= PASS A : row sums (QT=32) =======================
// smem words: Q[32*36=1152] K[2*4608] red[256]
#define A_QW 0
#define A_KW 1152
#define A_RW (A_KW + 9216)
#define A_SMB ((A_RW + 256) * 4)    // 42496 B

__global__ void __launch_bounds__(NTHR, 3)
rowsum_kernel(const float* __restrict__ Q) {
  extern __shared__ __align__(16) uint32_t smw[];
  const uint32_t sb = smem_u32(smw);
  const int tid = threadIdx.x;
  const int w = tid >> 5, lane = tid & 31;
  const int gid = lane >> 2, tg = lane & 3;
  const int bh = blockIdx.y;
  const int qt = (int)gridDim.x - 1 - (int)blockIdx.x;
  const int q0 = qt * QT;

  const float* Qg = Q + ((size_t)bh * S_DIM + q0) * 64;
  const char* Kg = (const char*)g_kh + (size_t)bh * 262144;

  { // stage Q (x 1/8) as fp16: 32 rows x 16 float4
    #pragma unroll
    for (int it = 0; it < 2; ++it) {
      int idx = tid + it * NTHR;
      int r = idx >> 4, f = idx & 15;
      float4 v = ((const float4*)Qg)[idx];
      ((uint2*)(smw + A_QW + r * 36 + 2 * f))[0] =
          make_uint2(packh2(v.x * 0.125f, v.y * 0.125f), packh2(v.z * 0.125f, v.w * 0.125f));
    }
  }
  { // prolog: K tile 0
    #pragma unroll
    for (int it = 0; it < 4; ++it) {
      int idx = tid + it * NTHR;
      int r = idx >> 3, c = idx & 7;
      CP16(sb + A_KW * 4 + r * 144 + c * 16, Kg + r * 128 + c * 16);
    }
    CP_COMMIT();
  }
  __syncthreads();

  uint32_t af[2][4][4];
  #pragma unroll
  for (int a = 0; a < 2; ++a)
    #pragma unroll
    for (int s = 0; s < 4; ++s) {
      af[a][s][0] = smw[A_QW + (gid + 16 * a) * 36 + 8 * s + tg];
      af[a][s][1] = smw[A_QW + (gid + 8 + 16 * a) * 36 + 8 * s + tg];
      af[a][s][2] = smw[A_QW + (gid + 16 * a) * 36 + 8 * s + 4 + tg];
      af[a][s][3] = smw[A_QW + (gid + 8 + 16 * a) * 36 + 8 * s + 4 + tg];
    }

  const int nkt = (q0 + QT + 127) >> 7;
  float rs[4] = {0.f, 0.f, 0.f, 0.f};

  for (int tt = 0; tt < nkt; ++tt) {
    const int kc = tt << 7;
    CP_WAIT0();
    __syncthreads();
    if (tt + 1 < nkt) {
      const char* kg1 = Kg + (size_t)(kc + KT) * 128;
      uint32_t kd = sb + (A_KW + ((tt + 1) & 1) * 4608) * 4;
      #pragma unroll
      for (int it = 0; it < 4; ++it) {
        int idx = tid + it * NTHR;
        int r = idx >> 3, c = idx & 7;
        CP16(kd + r * 144 + c * 16, kg1 + r * 128 + c * 16);
      }
      CP_COMMIT();
    }
    const uint32_t* kb = smw + A_KW + (tt & 1) * 4608;
    const int nc0 = (16 * w + gid) * 36, nc1 = (16 * w + 8 + gid) * 36;
    const int cg0 = kc + 16 * w + 2 * tg, cg1 = cg0 + 8;

    #pragma unroll
    for (int a = 0; a < 2; ++a) {
      float acc0[4] = {0.f, 0.f, 0.f, 0.f};
      float acc1[4] = {0.f, 0.f, 0.f, 0.f};
      #pragma unroll
      for (int s = 0; s < 4; ++s) {
        mma16(acc0, af[a][s], kb[nc0 + 8 * s + tg], kb[nc0 + 8 * s + 4 + tg]);
        mma16(acc1, af[a][s], kb[nc1 + 8 * s + tg], kb[nc1 + 8 * s + 4 + tg]);
      }
      const int ra = q0 + gid + 16 * a, rb = ra + 8;
      rs[2 * a] += ((cg0     <= ra) ? __expf(acc0[0]) : 0.f)
                 + ((cg0 + 1 <= ra) ? __expf(acc0[1]) : 0.f)
                 + ((cg1     <= ra) ? __expf(acc1[0]) : 0.f)
                 + ((cg1 + 1 <= ra) ? __expf(acc1[1]) : 0.f);
      rs[2 * a + 1] += ((cg0     <= rb) ? __expf(acc0[2]) : 0.f)
                     + ((cg0 + 1 <= rb) ? __expf(acc0[3]) : 0.f)
                     + ((cg1     <= rb) ? __expf(acc1[2]) : 0.f)
                     + ((cg1 + 1 <= rb) ? __expf(acc1[3]) : 0.f);
    }
  }

  #pragma unroll
  for (int u = 0; u < 4; ++u) {
    rs[u] += __shfl_xor_sync(~0u, rs[u], 1);
    rs[u] += __shfl_xor_sync(~0u, rs[u], 2);
  }
  float* red = (float*)(smw + A_RW);
  if (tg == 0) {
    red[w * 32 + gid]      = rs[0];
    red[w * 32 + gid + 8]  = rs[1];
    red[w * 32 + gid + 16] = rs[2];
    red[w * 32 + gid + 24] = rs[3];
  }
  __syncthreads();
  if (tid < 32) {
    float s = 0.f;
    #pragma unroll
    for (int i = 0; i < 8; ++i) s += red[i * 32 + tid];
    g_inv[bh * S_DIM + q0 + tid] = 1.0f / s;
  }
}

// ======================= PASS B : W + O (QT=32) =======================
// smem words: Q[1152] K[2*4608] V[2*4352] P[32*68=2176]
#define B_QW 0
#define B_KW 1152
#define B_VW (B_KW + 9216)           // 10368
#define B_PW (B_VW + 8704)           // 19072
#define B_SMB ((B_PW + 2176) * 4)    // 84992 B

__global__ void __launch_bounds__(NTHR, 2)
attn_pb_kernel(const float* __restrict__ Q, float* __restrict__ out) {
  extern __shared__ __align__(16) uint32_t smw[];
  const uint32_t sb = smem_u32(smw);
  const int tid = threadIdx.x;
  const int w = tid >> 5, lane = tid & 31;
  const int gid = lane >> 2, tg = lane & 3;
  const int bh = blockIdx.y;
  const int qt = (int)gridDim.x - 1 - (int)blockIdx.x;
  const int q0 = qt * QT;

  const float* Qg = Q + ((size_t)bh * S_DIM + q0) * 64;
  const char* Kg = (const char*)g_kh + (size_t)bh * 262144;
  const char* Vg = (const char*)g_vh + (size_t)bh * 262144;
  float* Og = out + ((size_t)bh * S_DIM + q0) * 64;
  float* Wg = out + OUT_O_ELEMS + ((size_t)bh * S_DIM + q0) * (size_t)S_DIM;

  const float iv0 = g_inv[bh * S_DIM + q0 + gid];
  const float iv1 = g_inv[bh * S_DIM + q0 + gid + 8];
  const float iv2 = g_inv[bh * S_DIM + q0 + gid + 16];
  const float iv3 = g_inv[bh * S_DIM + q0 + gid + 24];

  { // stage Q (x 1/8) as fp16
    #pragma unroll
    for (int it = 0; it < 2; ++it) {
      int idx = tid + it * NTHR;
      int r = idx >> 4, f = idx & 15;
      float4 v = ((const float4*)Qg)[idx];
      ((uint2*)(smw + B_QW + r * 36 + 2 * f))[0] =
          make_uint2(packh2(v.x * 0.125f, v.y * 0.125f), packh2(v.z * 0.125f, v.w * 0.125f));
    }
  }
  { // prolog: K + V tile 0
    #pragma unroll
    for (int it = 0; it < 4; ++it) {
      int idx = tid + it * NTHR;
      int r = idx >> 3, c = idx & 7;
      CP16(sb + B_KW * 4 + r * 144 + c * 16, Kg + r * 128 + c * 16);
    }
    #pragma unroll
    for (int it = 0; it < 4; ++it) {
      int idx = tid + it * NTHR;
      int k2 = idx >> 4, c = idx & 15;
      CP16(sb + B_VW * 4 + k2 * 272 + (((c << 2) + 4 * (k2 & 15)) & 63) * 4,
           Vg + k2 * 256 + c * 16);
    }
    CP_COMMIT();
  }
  __syncthreads();

  uint32_t af[2][4][4];
  #pragma unroll
  for (int a = 0; a < 2; ++a)
    #pragma unroll
    for (int s = 0; s < 4; ++s) {
      af[a][s][0] = smw[B_QW + (gid + 16 * a) * 36 + 8 * s + tg];
      af[a][s][1] = smw[B_QW + (gid + 8 + 16 * a) * 36 + 8 * s + tg];
      af[a][s][2] = smw[B_QW + (gid + 16 * a) * 36 + 8 * s + 4 + tg];
      af[a][s][3] = smw[B_QW + (gid + 8 + 16 * a) * 36 + 8 * s + 4 + tg];
    }

  const int nkt = (q0 + QT + 127) >> 7;
  float oc[8][4];
  #pragma unroll
  for (int j = 0; j < 8; ++j)
    #pragma unroll
    for (int u = 0; u < 4; ++u) oc[j][u] = 0.f;

  // PV role: warp = (atom a2, k32-slice s2)
  const int a2 = w >> 2, s2 = w & 3;
  uint32_t* pw = smw + B_PW;

  for (int tt = 0; tt < nkt; ++tt) {
    const int kc = tt << 7;
    CP_WAIT0();
    __syncthreads();
    if (tt + 1 < nkt) {
      const char* kg1 = Kg + (size_t)(kc + KT) * 128;
      const char* vg1 = Vg + (size_t)(kc >> 1) * 256 + 64 * 256;
      uint32_t kd = sb + (B_KW + ((tt + 1) & 1) * 4608) * 4;
      uint32_t vd = sb + (B_VW + ((tt + 1) & 1) * 4352) * 4;
      #pragma unroll
      for (int it = 0; it < 4; ++it) {
        int idx = tid + it * NTHR;
        int r = idx >> 3, c = idx & 7;
        CP16(kd + r * 144 + c * 16, kg1 + r * 128 + c * 16);
      }
      #pragma unroll
      for (int it = 0; it < 4; ++it) {
        int idx = tid + it * NTHR;
        int k2 = idx >> 4, c = idx & 15;
        CP16(vd + k2 * 272 + (((c << 2) + 4 * (k2 & 15)) & 63) * 4,
             vg1 + k2 * 256 + c * 16);
      }
      CP_COMMIT();
    }
    const uint32_t* kb = smw + B_KW + (tt & 1) * 4608;
    const uint32_t* vb = smw + B_VW + (tt & 1) * 4352;

    // ---- QK both atoms on warp's n16 strip; W(.cs) + P(smem) from regs ----
    const int nc0 = (16 * w + gid) * 36, nc1 = (16 * w + 8 + gid) * 36;
    const int cg0 = kc + 16 * w + 2 * tg, cg1 = cg0 + 8;
    const int k2w0 = 8 * w + tg, k2w1 = 8 * w + 4 + tg;
    #pragma unroll
    for (int a = 0; a < 2; ++a) {
      float acc0[4] = {0.f, 0.f, 0.f, 0.f};
      float acc1[4] = {0.f, 0.f, 0.f, 0.f};
      #pragma unroll
      for (int s = 0; s < 4; ++s) {
        mma16(acc0, af[a][s], kb[nc0 + 8 * s + tg], kb[nc0 + 8 * s + 4 + tg]);
        mma16(acc1, af[a][s], kb[nc1 + 8 * s + tg], kb[nc1 + 8 * s + 4 + tg]);
      }
      const int ra = q0 + gid + 16 * a, rb = ra + 8;
      const float iva = a ? iv2 : iv0, ivb = a ? iv3 : iv1;
      float e000 = (cg0     <= ra) ? __expf(acc0[0]) * iva : 0.f;
      float e001 = (cg0 + 1 <= ra) ? __expf(acc0[1]) * iva : 0.f;
      float e010 = (cg0     <= rb) ? __expf(acc0[2]) * ivb : 0.f;
      float e011 = (cg0 + 1 <= rb) ? __expf(acc0[3]) * ivb : 0.f;
      float e100 = (cg1     <= ra) ? __expf(acc1[0]) * iva : 0.f;
      float e101 = (cg1 + 1 <= ra) ? __expf(acc1[1]) * iva : 0.f;
      float e110 = (cg1     <= rb) ? __expf(acc1[2]) * ivb : 0.f;
      float e111 = (cg1 + 1 <= rb) ? __expf(acc1[3]) * ivb : 0.f;
      const int rla = gid + 16 * a, rlb = rla + 8;
      stg_cs2(&Wg[(size_t)rla * S_DIM + cg0], e000, e001);
      stg_cs2(&Wg[(size_t)rlb * S_DIM + cg0], e010, e011);
      stg_cs2(&Wg[(size_t)rla * S_DIM + cg1], e100, e101);
      stg_cs2(&Wg[(size_t)rlb * S_DIM + cg1], e110, e111);
      pw[rla * 68 + k2w0] = packh2(e000, e001);
      pw[rlb * 68 + k2w0] = packh2(e010, e011);
      pw[rla * 68 + k2w1] = packh2(e100, e101);
      pw[rlb * 68 + k2w1] = packh2(e110, e111);
    }
    __syncthreads();   // p tile complete before cross-warp PV reads

    // ---- PV: warp (a2, s2): rows of atom a2, k32 slice s2, all 64 d ----
    const int rpa = (gid + 16 * a2) * 68, rpb = (gid + 8 + 16 * a2) * 68;
    #pragma unroll
    for (int c = 0; c < 2; ++c) {
      const int base = 16 * s2 + 8 * c;
      uint32_t pa[4];
      pa[0] = pw[rpa + base + tg];
      pa[1] = pw[rpb + base + tg];
      pa[2] = pw[rpa + base + 4 + tg];
      pa[3] = pw[rpb + base + 4 + tg];
      const int k2a = base + tg, k2b = base + 4 + tg;
      const int swa = 4 * (k2a & 15), swb = 4 * (k2b & 15);
      #pragma unroll
      for (int j = 0; j < 8; ++j) {
        const int d = 8 * j + gid;
        uint32_t b0 = vb[k2a * 68 + ((d + swa) & 63)];
        uint32_t b1 = vb[k2b * 68 + ((d + swb) & 63)];
        mma16(oc[j], pa, b0, b1);
      }
    }
  }

  // ---- W zero tail (.cs) ----
  {
    const int ktend = nkt << 7;
    const int r = tid >> 3, f = tid & 7;
    float* wrow = Wg + (size_t)r * S_DIM;
    for (int c4 = (ktend >> 2) + f; c4 < (S_DIM >> 2); c4 += 8)
      stg_cs4z(wrow + 4 * c4);
  }

  // ---- O merge: 4 k-slice partials per atom via smem reuse ----
  __syncthreads();
  float* smf = (float*)smw;
  {
    float* osc = &smf[w * (16 * 66)];
    #pragma unroll
    for (int j = 0; j < 8; ++j) {
      *(float2*)&osc[gid * 66 + j * 8 + 2 * tg]       = make_float2(oc[j][0], oc[j][1]);
      *(float2*)&osc[(gid + 8) * 66 + j * 8 + 2 * tg] = make_float2(oc[j][2], oc[j][3]);
    }
  }
  __syncthreads();
  #pragma unroll
  for (int it = 0; it < 8; ++it) {
    const int e = tid + it * NTHR;
    const int r = e >> 6, d = e & 63;
    const int wbase = (r >> 4) * 4;
    const int rl = r & 15;
    float s = 0.f;
    #pragma unroll
    for (int p = 0; p < 4; ++p) s += smf[(wbase + p) * (16 * 66) + rl * 66 + d];
    Og[r * 64 + d] = s;
  }
}

extern "C" void kernel_launch(void* const* d_in, const int* in_sizes, int n_in,
                              void* d_out, int out_size) {
  (void)in_sizes; (void)n_in; (void)out_size;
  const float* q = (const float*)d_in[0];
  const float* k = (const float*)d_in[1];
  const float* v = (const float*)d_in[2];
  float* out = (float*)d_out;

  cudaFuncSetAttribute(rowsum_kernel,
                       cudaFuncAttributeMaxDynamicSharedMemorySize, A_SMB);
  cudaFuncSetAttribute(attn_pb_kernel,
                       cudaFuncAttributeMaxDynamicSharedMemorySize, B_SMB);
  dim3 grid(S_DIM / QT, 32);
  kv_prep_kernel<<<KV_ELEMS / 4 / 256, 256>>>(k, v);
  rowsum_kernel<<<grid, NTHR, A_SMB>>>(q);
  attn_pb_kernel<<<grid, NTHR, B_SMB>>>(q, out);
}

// round 17
// speedup vs baseline: 1.2060x; 1.0965x over previous
#include <cuda_runtime.h>
#include <cstdint>

#define S_DIM 2048
#define QT 32
#define KT 128
#define NTHR 256
#define OUT_O_ELEMS 4194304ull
#define KV_ELEMS 4194304
#define QSCALE 0.180336880111112f   // 0.125 * log2(e)

__device__ float    g_inv[65536];          // 1/rowsum per (bh,row)
__device__ uint32_t g_kh[KV_ELEMS / 2];    // K fp16 (half2 words along d)
__device__ uint32_t g_vh[KV_ELEMS / 2];    // V fp16, k-paired

__device__ __forceinline__ uint32_t smem_u32(const void* p) {
  uint32_t a;
  asm("{ .reg .u64 t; cvta.to.shared.u64 t, %1; cvt.u32.u64 %0, t; }" : "=r"(a) : "l"(p));
  return a;
}
__device__ __forceinline__ uint32_t packh2(float lo, float hi) {
  uint32_t r; asm("cvt.rn.f16x2.f32 %0, %1, %2;" : "=r"(r) : "f"(hi), "f"(lo));
  return r;
}
__device__ __forceinline__ float ex2f(float x) {
  float r; asm("ex2.approx.f32 %0, %1;" : "=f"(r) : "f"(x));
  return r;
}
__device__ __forceinline__ void mma16(float c[4], const uint32_t a[4],
                                      uint32_t b0, uint32_t b1) {
  asm volatile("mma.sync.aligned.m16n8k16.row.col.f32.f16.f16.f32 "
    "{%0,%1,%2,%3}, {%4,%5,%6,%7}, {%8,%9}, {%0,%1,%2,%3};"
    : "+f"(c[0]), "+f"(c[1]), "+f"(c[2]), "+f"(c[3])
    : "r"(a[0]), "r"(a[1]), "r"(a[2]), "r"(a[3]), "r"(b0), "r"(b1));
}
__device__ __forceinline__ void stg_cs2(float* p, float x, float y) {
  asm volatile("st.global.cs.v2.f32 [%0], {%1, %2};" :: "l"(p), "f"(x), "f"(y) : "memory");
}
__device__ __forceinline__ void stg_cs4z(float* p) {
  asm volatile("st.global.cs.v4.f32 [%0], {%1, %1, %1, %1};" :: "l"(p), "f"(0.f) : "memory");
}
#define CP16(dst, src) asm volatile("cp.async.ca.shared.global [%0], [%1], 16;" :: "r"(dst), "l"(src) : "memory")
#define CP_COMMIT()    asm volatile("cp.async.commit_group;" ::: "memory")
#define CP_WAIT0()     asm volatile("cp.async.wait_group 0;" ::: "memory")

// =================== PREP : K,V -> fp16 (V k-paired) ===================
__global__ void __launch_bounds__(256)
kv_prep_kernel(const float* __restrict__ K, const float* __restrict__ V) {
  const int i = blockIdx.x * 256 + threadIdx.x;
  float4 k = ((const float4*)K)[i];
  ((uint2*)g_kh)[i] = make_uint2(packh2(k.x, k.y), packh2(k.z, k.w));
  const int k2g = i >> 5, d2 = i & 31;
  const float2* v0 = (const float2*)(V + (size_t)k2g * 128);
  float2 a = v0[d2], b = v0[32 + d2];
  ((uint2*)g_vh)[(size_t)k2g * 32 + d2] = make_uint2(packh2(a.x, b.x), packh2(a.y, b.y));
}

// ======================= PASS A : row sums (QT=32) =======================
// smem words: Q[32*36=1152] K[2*4608] red[256]
#define A_QW 0
#define A_KW 1152
#define A_RW (A_KW + 9216)
#define A_SMB ((A_RW + 256) * 4)    // 42496 B

__global__ void __launch_bounds__(NTHR, 3)
rowsum_kernel(const float* __restrict__ Q) {
  extern __shared__ __align__(16) uint32_t smw[];
  const uint32_t sb = smem_u32(smw);
  const int tid = threadIdx.x;
  const int w = tid >> 5, lane = tid & 31;
  const int gid = lane >> 2, tg = lane & 3;
  const int bh = blockIdx.y;
  const int qt = (int)gridDim.x - 1 - (int)blockIdx.x;
  const int q0 = qt * QT;

  const float* Qg = Q + ((size_t)bh * S_DIM + q0) * 64;
  const char* Kg = (const char*)g_kh + (size_t)bh * 262144;

  { // stage Q (x QSCALE) as fp16: 32 rows x 16 float4
    #pragma unroll
    for (int it = 0; it < 2; ++it) {
      int idx = tid + it * NTHR;
      int r = idx >> 4, f = idx & 15;
      float4 v = ((const float4*)Qg)[idx];
      ((uint2*)(smw + A_QW + r * 36 + 2 * f))[0] =
          make_uint2(packh2(v.x * QSCALE, v.y * QSCALE), packh2(v.z * QSCALE, v.w * QSCALE));
    }
  }
  { // prolog: K tile 0
    #pragma unroll
    for (int it = 0; it < 4; ++it) {
      int idx = tid + it * NTHR;
      int r = idx >> 3, c = idx & 7;
      CP16(sb + A_KW * 4 + r * 144 + c * 16, Kg + r * 128 + c * 16);
    }
    CP_COMMIT();
  }
  __syncthreads();

  uint32_t af[2][4][4];
  #pragma unroll
  for (int a = 0; a < 2; ++a)
    #pragma unroll
    for (int s = 0; s < 4; ++s) {
      af[a][s][0] = smw[A_QW + (gid + 16 * a) * 36 + 8 * s + tg];
      af[a][s][1] = smw[A_QW + (gid + 8 + 16 * a) * 36 + 8 * s + tg];
      af[a][s][2] = smw[A_QW + (gid + 16 * a) * 36 + 8 * s + 4 + tg];
      af[a][s][3] = smw[A_QW + (gid + 8 + 16 * a) * 36 + 8 * s + 4 + tg];
    }

  const int nkt = (q0 + QT + 127) >> 7;
  float rs[4] = {0.f, 0.f, 0.f, 0.f};

  for (int tt = 0; tt < nkt; ++tt) {
    const int kc = tt << 7;
    CP_WAIT0();
    __syncthreads();
    if (tt + 1 < nkt) {
      const char* kg1 = Kg + (size_t)(kc + KT) * 128;
      uint32_t kd = sb + (A_KW + ((tt + 1) & 1) * 4608) * 4;
      #pragma unroll
      for (int it = 0; it < 4; ++it) {
        int idx = tid + it * NTHR;
        int r = idx >> 3, c = idx & 7;
        CP16(kd + r * 144 + c * 16, kg1 + r * 128 + c * 16);
      }
      CP_COMMIT();
    }
    const uint32_t* kb = smw + A_KW + (tt & 1) * 4608;
    const int nc0 = (16 * w + gid) * 36, nc1 = (16 * w + 8 + gid) * 36;
    const int cg0 = kc + 16 * w + 2 * tg, cg1 = cg0 + 8;
    const bool bdry = (tt == nkt - 1);

    #pragma unroll
    for (int a = 0; a < 2; ++a) {
      float acc0[4] = {0.f, 0.f, 0.f, 0.f};
      float acc1[4] = {0.f, 0.f, 0.f, 0.f};
      #pragma unroll
      for (int s = 0; s < 4; ++s) {
        mma16(acc0, af[a][s], kb[nc0 + 8 * s + tg], kb[nc0 + 8 * s + 4 + tg]);
        mma16(acc1, af[a][s], kb[nc1 + 8 * s + tg], kb[nc1 + 8 * s + 4 + tg]);
      }
      if (bdry) {
        const int ra = q0 + gid + 16 * a, rb = ra + 8;
        rs[2 * a] += ((cg0     <= ra) ? ex2f(acc0[0]) : 0.f)
                   + ((cg0 + 1 <= ra) ? ex2f(acc0[1]) : 0.f)
                   + ((cg1     <= ra) ? ex2f(acc1[0]) : 0.f)
                   + ((cg1 + 1 <= ra) ? ex2f(acc1[1]) : 0.f);
        rs[2 * a + 1] += ((cg0     <= rb) ? ex2f(acc0[2]) : 0.f)
                       + ((cg0 + 1 <= rb) ? ex2f(acc0[3]) : 0.f)
                       + ((cg1     <= rb) ? ex2f(acc1[2]) : 0.f)
                       + ((cg1 + 1 <= rb) ? ex2f(acc1[3]) : 0.f);
      } else {
        rs[2 * a]     += ex2f(acc0[0]) + ex2f(acc0[1]) + ex2f(acc1[0]) + ex2f(acc1[1]);
        rs[2 * a + 1] += ex2f(acc0[2]) + ex2f(acc0[3]) + ex2f(acc1[2]) + ex2f(acc1[3]);
      }
    }
  }

  #pragma unroll
  for (int u = 0; u < 4; ++u) {
    rs[u] += __shfl_xor_sync(~0u, rs[u], 1);
    rs[u] += __shfl_xor_sync(~0u, rs[u], 2);
  }
  float* red = (float*)(smw + A_RW);
  if (tg == 0) {
    red[w * 32 + gid]      = rs[0];
    red[w * 32 + gid + 8]  = rs[1];
    red[w * 32 + gid + 16] = rs[2];
    red[w * 32 + gid + 24] = rs[3];
  }
  __syncthreads();
  if (tid < 32) {
    float s = 0.f;
    #pragma unroll
    for (int i = 0; i < 8; ++i) s += red[i * 32 + tid];
    g_inv[bh * S_DIM + q0 + tid] = 1.0f / s;
  }
}

// ======================= PASS B : W + O (QT=32) =======================
// smem words: Q[1152] K[2*4608] V[2*4352] P[32*68=2176]
#define B_QW 0
#define B_KW 1152
#define B_VW (B_KW + 9216)           // 10368
#define B_PW (B_VW + 8704)           // 19072
#define B_SMB ((B_PW + 2176) * 4)    // 84992 B

__global__ void __launch_bounds__(NTHR, 2)
attn_pb_kernel(const float* __restrict__ Q, float* __restrict__ out) {
  extern __shared__ __align__(16) uint32_t smw[];
  const uint32_t sb = smem_u32(smw);
  const int tid = threadIdx.x;
  const int w = tid >> 5, lane = tid & 31;
  const int gid = lane >> 2, tg = lane & 3;
  const int bh = blockIdx.y;
  const int qt = (int)gridDim.x - 1 - (int)blockIdx.x;
  const int q0 = qt * QT;

  const float* Qg = Q + ((size_t)bh * S_DIM + q0) * 64;
  const char* Kg = (const char*)g_kh + (size_t)bh * 262144;
  const char* Vg = (const char*)g_vh + (size_t)bh * 262144;
  float* Og = out + ((size_t)bh * S_DIM + q0) * 64;
  float* Wg = out + OUT_O_ELEMS + ((size_t)bh * S_DIM + q0) * (size_t)S_DIM;

  const float iv0 = g_inv[bh * S_DIM + q0 + gid];
  const float iv1 = g_inv[bh * S_DIM + q0 + gid + 8];
  const float iv2 = g_inv[bh * S_DIM + q0 + gid + 16];
  const float iv3 = g_inv[bh * S_DIM + q0 + gid + 24];

  { // stage Q (x QSCALE) as fp16
    #pragma unroll
    for (int it = 0; it < 2; ++it) {
      int idx = tid + it * NTHR;
      int r = idx >> 4, f = idx & 15;
      float4 v = ((const float4*)Qg)[idx];
      ((uint2*)(smw + B_QW + r * 36 + 2 * f))[0] =
          make_uint2(packh2(v.x * QSCALE, v.y * QSCALE), packh2(v.z * QSCALE, v.w * QSCALE));
    }
  }
  { // prolog: K + V tile 0
    #pragma unroll
    for (int it = 0; it < 4; ++it) {
      int idx = tid + it * NTHR;
      int r = idx >> 3, c = idx & 7;
      CP16(sb + B_KW * 4 + r * 144 + c * 16, Kg + r * 128 + c * 16);
    }
    #pragma unroll
    for (int it = 0; it < 4; ++it) {
      int idx = tid + it * NTHR;
      int k2 = idx >> 4, c = idx & 15;
      CP16(sb + B_VW * 4 + k2 * 272 + (((c << 2) + 4 * (k2 & 15)) & 63) * 4,
           Vg + k2 * 256 + c * 16);
    }
    CP_COMMIT();
  }
  __syncthreads();

  uint32_t af[2][4][4];
  #pragma unroll
  for (int a = 0; a < 2; ++a)
    #pragma unroll
    for (int s = 0; s < 4; ++s) {
      af[a][s][0] = smw[B_QW + (gid + 16 * a) * 36 + 8 * s + tg];
      af[a][s][1] = smw[B_QW + (gid + 8 + 16 * a) * 36 + 8 * s + tg];
      af[a][s][2] = smw[B_QW + (gid + 16 * a) * 36 + 8 * s + 4 + tg];
      af[a][s][3] = smw[B_QW + (gid + 8 + 16 * a) * 36 + 8 * s + 4 + tg];
    }

  const int nkt = (q0 + QT + 127) >> 7;
  float oc[8][4];
  #pragma unroll
  for (int j = 0; j < 8; ++j)
    #pragma unroll
    for (int u = 0; u < 4; ++u) oc[j][u] = 0.f;

  // PV role: warp = (atom a2, k32-slice s2)
  const int a2 = w >> 2, s2 = w & 3;
  uint32_t* pw = smw + B_PW;

  for (int tt = 0; tt < nkt; ++tt) {
    const int kc = tt << 7;
    CP_WAIT0();
    __syncthreads();
    if (tt + 1 < nkt) {
      const char* kg1 = Kg + (size_t)(kc + KT) * 128;
      const char* vg1 = Vg + (size_t)(kc >> 1) * 256 + 64 * 256;
      uint32_t kd = sb + (B_KW + ((tt + 1) & 1) * 4608) * 4;
      uint32_t vd = sb + (B_VW + ((tt + 1) & 1) * 4352) * 4;
      #pragma unroll
      for (int it = 0; it < 4; ++it) {
        int idx = tid + it * NTHR;
        int r = idx >> 3, c = idx & 7;
        CP16(kd + r * 144 + c * 16, kg1 + r * 128 + c * 16);
      }
      #pragma unroll
      for (int it = 0; it < 4; ++it) {
        int idx = tid + it * NTHR;
        int k2 = idx >> 4, c = idx & 15;
        CP16(vd + k2 * 272 + (((c << 2) + 4 * (k2 & 15)) & 63) * 4,
             vg1 + k2 * 256 + c * 16);
      }
      CP_COMMIT();
    }
    const uint32_t* kb = smw + B_KW + (tt & 1) * 4608;
    const uint32_t* vb = smw + B_VW + (tt & 1) * 4352;

    // ---- QK both atoms on warp's n16 strip; W(.cs) + P(smem) from regs ----
    const int nc0 = (16 * w + gid) * 36, nc1 = (16 * w + 8 + gid) * 36;
    const int cg0 = kc + 16 * w + 2 * tg, cg1 = cg0 + 8;
    const int k2w0 = 8 * w + tg, k2w1 = 8 * w + 4 + tg;
    const bool bdry = (tt == nkt - 1);
    #pragma unroll
    for (int a = 0; a < 2; ++a) {
      float acc0[4] = {0.f, 0.f, 0.f, 0.f};
      float acc1[4] = {0.f, 0.f, 0.f, 0.f};
      #pragma unroll
      for (int s = 0; s < 4; ++s) {
        mma16(acc0, af[a][s], kb[nc0 + 8 * s + tg], kb[nc0 + 8 * s + 4 + tg]);
        mma16(acc1, af[a][s], kb[nc1 + 8 * s + tg], kb[nc1 + 8 * s + 4 + tg]);
      }
      const float iva = a ? iv2 : iv0, ivb = a ? iv3 : iv1;
      float e000, e001, e010, e011, e100, e101, e110, e111;
      if (bdry) {
        const int ra = q0 + gid + 16 * a, rb = ra + 8;
        e000 = (cg0     <= ra) ? ex2f(acc0[0]) * iva : 0.f;
        e001 = (cg0 + 1 <= ra) ? ex2f(acc0[1]) * iva : 0.f;
        e010 = (cg0     <= rb) ? ex2f(acc0[2]) * ivb : 0.f;
        e011 = (cg0 + 1 <= rb) ? ex2f(acc0[3]) * ivb : 0.f;
        e100 = (cg1     <= ra) ? ex2f(acc1[0]) * iva : 0.f;
        e101 = (cg1 + 1 <= ra) ? ex2f(acc1[1]) * iva : 0.f;
        e110 = (cg1     <= rb) ? ex2f(acc1[2]) * ivb : 0.f;
        e111 = (cg1 + 1 <= rb) ? ex2f(acc1[3]) * ivb : 0.f;
      } else {
        e000 = ex2f(acc0[0]) * iva;
        e001 = ex2f(acc0[1]) * iva;
        e010 = ex2f(acc0[2]) * ivb;
        e011 = ex2f(acc0[3]) * ivb;
        e100 = ex2f(acc1[0]) * iva;
        e101 = ex2f(acc1[1]) * iva;
        e110 = ex2f(acc1[2]) * ivb;
        e111 = ex2f(acc1[3]) * ivb;
      }
      const int rla = gid + 16 * a, rlb = rla + 8;
      stg_cs2(&Wg[(size_t)rla * S_DIM + cg0], e000, e001);
      stg_cs2(&Wg[(size_t)rlb * S_DIM + cg0], e010, e011);
      stg_cs2(&Wg[(size_t)rla * S_DIM + cg1], e100, e101);
      stg_cs2(&Wg[(size_t)rlb * S_DIM + cg1], e110, e111);
      pw[rla * 68 + k2w0] = packh2(e000, e001);
      pw[rlb * 68 + k2w0] = packh2(e010, e011);
      pw[rla * 68 + k2w1] = packh2(e100, e101);
      pw[rlb * 68 + k2w1] = packh2(e110, e111);
    }
    __syncthreads();   // p tile complete before cross-warp PV reads

    // ---- PV: warp (a2, s2): rows of atom a2, k32 slice s2, all 64 d ----
    const int rpa = (gid + 16 * a2) * 68, rpb = (gid + 8 + 16 * a2) * 68;
    #pragma unroll
    for (int c = 0; c < 2; ++c) {
      const int base = 16 * s2 + 8 * c;
      uint32_t pa[4];
      pa[0] = pw[rpa + base + tg];
      pa[1] = pw[rpb + base + tg];
      pa[2] = pw[rpa + base + 4 + tg];
      pa[3] = pw[rpb + base + 4 + tg];
      const int k2a = base + tg, k2b = base + 4 + tg;
      const int swa = 4 * (k2a & 15), swb = 4 * (k2b & 15);
      #pragma unroll
      for (int j = 0; j < 8; ++j) {
        const int d = 8 * j + gid;
        uint32_t b0 = vb[k2a * 68 + ((d + swa) & 63)];
        uint32_t b1 = vb[k2b * 68 + ((d + swb) & 63)];
        mma16(oc[j], pa, b0, b1);
      }
    }
  }

  // ---- W zero tail (.cs) ----
  {
    const int ktend = nkt << 7;
    const int r = tid >> 3, f = tid & 7;
    float* wrow = Wg + (size_t)r * S_DIM;
    for (int c4 = (ktend >> 2) + f; c4 < (S_DIM >> 2); c4 += 8)
      stg_cs4z(wrow + 4 * c4);
  }

  // ---- O merge: 4 k-slice partials per atom via smem reuse ----
  __syncthreads();
  float* smf = (float*)smw;
  {
    float* osc = &smf[w * (16 * 66)];
    #pragma unroll
    for (int j = 0; j < 8; ++j) {
      *(float2*)&osc[gid * 66 + j * 8 + 2 * tg]       = make_float2(oc[j][0], oc[j][1]);
      *(float2*)&osc[(gid + 8) * 66 + j * 8 + 2 * tg] = make_float2(oc[j][2], oc[j][3]);
    }
  }
  __syncthreads();
  #pragma unroll
  for (int it = 0; it < 8; ++it) {
    const int e = tid + it * NTHR;
    const int r = e >> 6, d = e & 63;
    const int wbase = (r >> 4) * 4;
    const int rl = r & 15;
    float s = 0.f;
    #pragma unroll
    for (int p = 0; p < 4; ++p) s += smf[(wbase + p) * (16 * 66) + rl * 66 + d];
    Og[r * 64 + d] = s;
  }
}

extern "C" void kernel_launch(void* const* d_in, const int* in_sizes, int n_in,
                              void* d_out, int out_size) {
  (void)in_sizes; (void)n_in; (void)out_size;
  const float* q = (const float*)d_in[0];
  const float* k = (const float*)d_in[1];
  const float* v = (const float*)d_in[2];
  float* out = (float*)d_out;

  cudaFuncSetAttribute(rowsum_kernel,
                       cudaFuncAttributeMaxDynamicSharedMemorySize, A_SMB);
  cudaFuncSetAttribute(attn_pb_kernel,
                       cudaFuncAttributeMaxDynamicSharedMemorySize, B_SMB);
  dim3 grid(S_DIM / QT, 32);
  kv_prep_kernel<<<KV_ELEMS / 4 / 256, 256>>>(k, v);
  rowsum_kernel<<<grid, NTHR, A_SMB>>>(q);
  attn_pb_kernel<<<grid, NTHR, B_SMB>>>(q, out);
}